// round 12
// baseline (speedup 1.0000x reference)
#include <cuda_runtime.h>
#include <math.h>
#include <stdint.h>

#define N_NODES 50000
#define D 300
#define N_EDGES 800000
#define KP 320                      // padded K per plane (bf16 elems), row = 640 B
#define MROWS (N_NODES + 128)       // row padding so cp.async never reads OOB

// ---------------- device scratch (no allocations allowed) ----------------
__device__ __align__(16) float g_x1[N_NODES * D];            // f32 x1 (gather-2 input)
// bf16 hi/lo planes, [MROWS][KP] row-major; pads stay zero (zero-init, never written)
__device__ __align__(16) uint16_t g_fh [MROWS * KP];
__device__ __align__(16) uint16_t g_fl [MROWS * KP];
__device__ __align__(16) uint16_t g_ah [MROWS * KP];
__device__ __align__(16) uint16_t g_al [MROWS * KP];
__device__ __align__(16) uint16_t g_x1h[MROWS * KP];
__device__ __align__(16) uint16_t g_x1l[MROWS * KP];
__device__ __align__(16) uint16_t g_x2h[MROWS * KP];
__device__ __align__(16) uint16_t g_x2l[MROWS * KP];
// fragment-ordered split weights: [kstep][n8t(40)][lane(32)] -> {hi.b0, hi.b1, lo.b0, lo.b1}
__device__ uint4 g_Wf1[40 * 40 * 32];
__device__ uint4 g_Wf2[40 * 40 * 32];
__device__ uint4 g_Wf3[20 * 40 * 32];
// CSR
__device__ int g_count [N_NODES];
__device__ int g_indptr[N_NODES + 1];
__device__ int g_esrc  [N_EDGES];
__device__ int g_bsum[256];
__device__ int g_boff[256];
__device__ float g_partials[4096];
__device__ float g_inv_norm;

// ---------------- helpers ----------------
__device__ __forceinline__ uint32_t smem_u32(const void* p) {
    uint32_t a;
    asm("{ .reg .u64 t; cvta.to.shared.u64 t, %1; cvt.u32.u64 %0, t; }" : "=r"(a) : "l"(p));
    return a;
}
__device__ __forceinline__ uint32_t pack_bf16x2(float e, float o) {
    uint32_t r;
    asm("cvt.rn.bf16x2.f32 %0, %1, %2;" : "=r"(r) : "f"(o), "f"(e));
    return r;
}
__device__ __forceinline__ void split2(float e, float o, uint32_t& hi, uint32_t& lo) {
    hi = pack_bf16x2(e, o);
    float he = __uint_as_float(hi << 16);
    float ho = __uint_as_float(hi & 0xFFFF0000u);
    lo = pack_bf16x2(e - he, o - ho);
}

// ---------------- CSR build ----------------
__global__ void hist_kernel(const int* __restrict__ dst) {
    int e = blockIdx.x * 256 + threadIdx.x;
    if (e < N_EDGES) atomicAdd(&g_count[__ldg(&dst[e])], 1);
}
__global__ void partial_kernel() {
    __shared__ int sh[256];
    int i = blockIdx.x * 256 + threadIdx.x;
    sh[threadIdx.x] = (i < N_NODES) ? g_count[i] : 0;
    __syncthreads();
    for (int s = 128; s > 0; s >>= 1) {
        if (threadIdx.x < s) sh[threadIdx.x] += sh[threadIdx.x + s];
        __syncthreads();
    }
    if (threadIdx.x == 0) g_bsum[blockIdx.x] = sh[0];
}
__global__ void scanb_kernel(int nb) {
    __shared__ int sh[256];
    int v = (threadIdx.x < nb) ? g_bsum[threadIdx.x] : 0;
    sh[threadIdx.x] = v;
    __syncthreads();
    for (int off = 1; off < 256; off <<= 1) {
        int t = (threadIdx.x >= off) ? sh[threadIdx.x - off] : 0;
        __syncthreads();
        sh[threadIdx.x] += t;
        __syncthreads();
    }
    g_boff[threadIdx.x] = sh[threadIdx.x] - v;
}
__global__ void local_scan_kernel() {
    __shared__ int sh[256];
    int i = blockIdx.x * 256 + threadIdx.x;
    int v = (i < N_NODES) ? g_count[i] : 0;
    sh[threadIdx.x] = v;
    __syncthreads();
    for (int off = 1; off < 256; off <<= 1) {
        int t = (threadIdx.x >= off) ? sh[threadIdx.x - off] : 0;
        __syncthreads();
        sh[threadIdx.x] += t;
        __syncthreads();
    }
    if (i < N_NODES) g_indptr[i + 1] = g_boff[blockIdx.x] + sh[threadIdx.x];
    if (i == 0) g_indptr[0] = 0;
}
__global__ void fill_kernel(const int* __restrict__ src, const int* __restrict__ dst) {
    int e = blockIdx.x * 256 + threadIdx.x;
    if (e < N_EDGES) {
        int d = __ldg(&dst[e]);
        int old = atomicAdd(&g_count[d], -1);      // restores g_count to 0
        g_esrc[g_indptr[d] + old - 1] = __ldg(&src[e]);
    }
}

// ---------------- convert feat f32 -> hi/lo planes ----------------
__global__ void convert_feat_kernel(const float* __restrict__ feat) {
    int idx = blockIdx.x * 256 + threadIdx.x;
    if (idx >= N_NODES * 75) return;
    int m = idx / 75, c = idx - m * 75;
    float4 f = reinterpret_cast<const float4*>(feat)[idx];
    uint32_t h0, l0, h1, l1;
    split2(f.x, f.y, h0, l0);
    split2(f.z, f.w, h1, l1);
    reinterpret_cast<uint2*>(g_fh)[m * 80 + c] = make_uint2(h0, h1);
    reinterpret_cast<uint2*>(g_fl)[m * 80 + c] = make_uint2(l0, l1);
}

// ---------------- gather: agg planes = split( sum feat[esrc[j]] ) ----------------
__global__ __launch_bounds__(320)
void gather_kernel(const float* __restrict__ feat) {
    int nl = threadIdx.x / 75;
    int c  = threadIdx.x - nl * 75;
    if (nl >= 4) return;
    int v = blockIdx.x * 4 + nl;
    if (v >= N_NODES) return;
    int beg = __ldg(&g_indptr[v]), end = __ldg(&g_indptr[v + 1]);
    const float4* f4 = reinterpret_cast<const float4*>(feat);
    float4 acc = make_float4(0.f, 0.f, 0.f, 0.f);
    int j = beg;
    for (; j + 1 < end; j += 2) {
        int s0 = __ldg(&g_esrc[j]);
        int s1 = __ldg(&g_esrc[j + 1]);
        float4 a = f4[(long long)s0 * 75 + c];
        float4 b = f4[(long long)s1 * 75 + c];
        acc.x += a.x; acc.y += a.y; acc.z += a.z; acc.w += a.w;
        acc.x += b.x; acc.y += b.y; acc.z += b.z; acc.w += b.w;
    }
    if (j < end) {
        int s0 = __ldg(&g_esrc[j]);
        float4 a = f4[(long long)s0 * 75 + c];
        acc.x += a.x; acc.y += a.y; acc.z += a.z; acc.w += a.w;
    }
    uint32_t h0, l0, h1, l1;
    split2(acc.x, acc.y, h0, l0);
    split2(acc.z, acc.w, h1, l1);
    reinterpret_cast<uint2*>(g_ah)[v * 80 + c] = make_uint2(h0, h1);
    reinterpret_cast<uint2*>(g_al)[v * 80 + c] = make_uint2(l0, l1);
}

// ---------------- prep: split W into fragment-ordered hi/lo, plane-padded ----------------
__global__ void prep_w_kernel(const float* __restrict__ W1,
                              const float* __restrict__ W2,
                              const float* __restrict__ W3) {
    int idx = blockIdx.x * 256 + threadIdx.x;      // 500*256 = 128000 exactly
    const float* W; uint4* out; int K; int rel;
    if (idx < 51200)       { W = W1; out = g_Wf1; K = 600; rel = idx; }
    else if (idx < 102400) { W = W2; out = g_Wf2; K = 600; rel = idx - 51200; }
    else                   { W = W3; out = g_Wf3; K = 300; rel = idx - 102400; }
    int lane  = rel & 31;
    int n8t   = (rel >> 5) % 40;
    int kstep = rel / (40 * 32);
    int plane = kstep / 20, kwp = kstep % 20;
    int n  = n8t * 8 + (lane >> 2);
    int kb = kwp * 16 + (lane & 3) * 2;
    int ks[4] = { kb, kb + 1, kb + 8, kb + 9 };
    float v[4];
#pragma unroll
    for (int i = 0; i < 4; i++) {
        int kg = plane * 300 + ks[i];
        v[i] = (n < D && ks[i] < 300 && kg < K) ? W[(long long)n * K + kg] : 0.f;
    }
    uint32_t h0, l0, h1, l1;
    split2(v[0], v[1], h0, l0);
    split2(v[2], v[3], h1, l1);
    out[rel] = make_uint4(h0, h1, l0, l1);
}

// ---------------- bf16 3-pass split GEMM: FULL-N CTA (A read exactly once) ----------------
// CTA: BM=128, BN=320 (2 N-warps x 160); 8 warps = 4(M) x 2(N); grid = 391.
// A: cp.async planes (3 bufs x hi/lo x 8KB); B: cp.async 3 bufs x 40KB (L2-resident).
// One LDS.128 per n-tile feeds all 6 MMAs (bh=xy, bl=zw). acc = 160 regs/thread.
// EPI: 0 = lrelu -> Cf + planes, 1 = planes only, 2 = tanh -> Cf + sumsq
template<int NPLANES, int EPI>
__global__ __launch_bounds__(256, 1)
void gemm_mma(const uint16_t* __restrict__ A1h, const uint16_t* __restrict__ A1l,
              const uint16_t* __restrict__ A2h, const uint16_t* __restrict__ A2l,
              const uint4* __restrict__ Wf, const float* __restrict__ bias,
              float* __restrict__ Cf, uint16_t* __restrict__ Ph, uint16_t* __restrict__ Pl)
{
    extern __shared__ char smem[];
    const int T = NPLANES * 10;
    const int NT = 20;                             // n8-tiles per warp (160 cols)
    const int B_OFF = 49152;                       // A: 3 bufs x 2 variants x 8KB
    const int BBUF = 40960;                        // B per buffer (2 k16t x 40 n8t x 512B)

    const uint32_t sb = smem_u32(smem);
    const int tid = threadIdx.x, lane = tid & 31, wid = tid >> 5;
    const int warpM = wid >> 1, warpN = wid & 1;
    const int m0 = blockIdx.x * 128;

    float acc[2][NT][4];
#pragma unroll
    for (int mt = 0; mt < 2; mt++)
#pragma unroll
        for (int nt = 0; nt < NT; nt++)
#pragma unroll
            for (int r = 0; r < 4; r++) acc[mt][nt][r] = 0.f;

    auto cpChunk = [&](int t) {
        const int buf = t % 3;
        const int plane = (NPLANES == 2 && t >= 10) ? 1 : 0;
        const int tc = t - plane * 10;
        const uint8_t* ph = (const uint8_t*)(plane ? A2h : A1h);
        const uint8_t* pl = (const uint8_t*)(plane ? A2l : A1l);
#pragma unroll
        for (int i = 0; i < 2; i++) {
            int L = i * 256 + tid;                 // 0..511
            int row = L >> 2, q = L & 3;
            size_t goff = (size_t)(m0 + row) * 640 + tc * 64 + q * 16;
            int sw = q ^ ((row >> 1) & 3);
            uint32_t soff = (uint32_t)(row * 64 + sw * 16);
            asm volatile("cp.async.cg.shared.global [%0], [%1], 16;"
                         :: "r"(sb + (buf * 2 + 0) * 8192 + soff), "l"(ph + goff) : "memory");
            asm volatile("cp.async.cg.shared.global [%0], [%1], 16;"
                         :: "r"(sb + (buf * 2 + 1) * 8192 + soff), "l"(pl + goff) : "memory");
        }
#pragma unroll
        for (int i = 0; i < 10; i++) {             // 2560 uint4 per chunk
            int L = i * 256 + tid;
            int k16t = L / 1280, n8 = (L >> 5) % 40, ln = L & 31;
            const uint4* g = &Wf[((size_t)((t * 2 + k16t) * 40 + n8)) * 32 + ln];
            asm volatile("cp.async.cg.shared.global [%0], [%1], 16;"
                         :: "r"(sb + B_OFF + buf * BBUF + (uint32_t)L * 16), "l"(g) : "memory");
        }
        asm volatile("cp.async.commit_group;" ::: "memory");
    };

#define MMA_BF16(ACC, AF, B0, B1)                                                 \
    asm volatile(                                                                 \
        "mma.sync.aligned.m16n8k16.row.col.f32.bf16.bf16.f32 "                    \
        "{%0, %1, %2, %3}, {%4, %5, %6, %7}, {%8, %9}, {%0, %1, %2, %3};"         \
        : "+f"((ACC)[0]), "+f"((ACC)[1]), "+f"((ACC)[2]), "+f"((ACC)[3])          \
        : "r"((AF)[0]), "r"((AF)[1]), "r"((AF)[2]), "r"((AF)[3]),                 \
          "r"(B0), "r"(B1))

    cpChunk(0);
    cpChunk(1);

    for (int t = 0; t < T; t++) {
        const int buf = t % 3;
        asm volatile("cp.async.wait_group 1;" ::: "memory");
        __syncthreads();
        if (t + 2 < T) cpChunk(t + 2);

#pragma unroll
        for (int k16t = 0; k16t < 2; k16t++) {
            uint32_t ah[2][4], al[2][4];
            const int rowl = lane & 15;
            const int chunk = k16t * 2 + (lane >> 4);
#pragma unroll
            for (int mt = 0; mt < 2; mt++) {
                int row = warpM * 32 + mt * 16 + rowl;
                uint32_t off = (uint32_t)(row * 64 + ((chunk ^ ((row >> 1) & 3)) * 16));
                asm volatile("ldmatrix.sync.aligned.m8n8.x4.shared.b16 {%0, %1, %2, %3}, [%4];"
                             : "=r"(ah[mt][0]), "=r"(ah[mt][1]), "=r"(ah[mt][2]), "=r"(ah[mt][3])
                             : "r"(sb + (buf * 2 + 0) * 8192 + off));
                asm volatile("ldmatrix.sync.aligned.m8n8.x4.shared.b16 {%0, %1, %2, %3}, [%4];"
                             : "=r"(al[mt][0]), "=r"(al[mt][1]), "=r"(al[mt][2]), "=r"(al[mt][3])
                             : "r"(sb + (buf * 2 + 1) * 8192 + off));
            }
            const uint32_t bbase = sb + B_OFF + buf * BBUF +
                                   (uint32_t)((k16t * 40 + warpN * NT) * 32 + lane) * 16;
            // nt pairs: one LDS.128 each, 12 MMAs interleaved (acc reuse distance 4)
#pragma unroll
            for (int nt = 0; nt < NT; nt += 2) {
                uint4 b0, b1;
                asm volatile("ld.shared.v4.b32 {%0, %1, %2, %3}, [%4];"
                             : "=r"(b0.x), "=r"(b0.y), "=r"(b0.z), "=r"(b0.w)
                             : "r"(bbase + (uint32_t)nt * 512));
                asm volatile("ld.shared.v4.b32 {%0, %1, %2, %3}, [%4];"
                             : "=r"(b1.x), "=r"(b1.y), "=r"(b1.z), "=r"(b1.w)
                             : "r"(bbase + (uint32_t)(nt + 1) * 512));
                MMA_BF16(acc[0][nt],     ah[0], b0.x, b0.y);
                MMA_BF16(acc[0][nt + 1], ah[0], b1.x, b1.y);
                MMA_BF16(acc[1][nt],     ah[1], b0.x, b0.y);
                MMA_BF16(acc[1][nt + 1], ah[1], b1.x, b1.y);
                MMA_BF16(acc[0][nt],     ah[0], b0.z, b0.w);
                MMA_BF16(acc[0][nt + 1], ah[0], b1.z, b1.w);
                MMA_BF16(acc[1][nt],     ah[1], b0.z, b0.w);
                MMA_BF16(acc[1][nt + 1], ah[1], b1.z, b1.w);
                MMA_BF16(acc[0][nt],     al[0], b0.x, b0.y);
                MMA_BF16(acc[0][nt + 1], al[0], b1.x, b1.y);
                MMA_BF16(acc[1][nt],     al[1], b0.x, b0.y);
                MMA_BF16(acc[1][nt + 1], al[1], b1.x, b1.y);
            }
        }
    }

    // ---- epilogue ----
    float sumsq = 0.f;
#pragma unroll
    for (int mt = 0; mt < 2; mt++) {
#pragma unroll
        for (int h = 0; h < 2; h++) {
            int m = m0 + warpM * 32 + mt * 16 + (lane >> 2) + h * 8;
            if (m < N_NODES) {
#pragma unroll
                for (int nt = 0; nt < NT; nt++) {
                    int n = warpN * 160 + nt * 8 + (lane & 3) * 2;
                    if (n < D) {
                        float v0 = acc[mt][nt][h * 2 + 0] + __ldg(&bias[n]);
                        float v1 = acc[mt][nt][h * 2 + 1] + __ldg(&bias[n + 1]);
                        if (EPI == 0) {
                            v0 = (v0 >= 0.f) ? v0 : 0.01f * v0;
                            v1 = (v1 >= 0.f) ? v1 : 0.01f * v1;
                        }
                        if (EPI == 2) {
                            v0 = tanhf(v0); v1 = tanhf(v1);
                            sumsq += v0 * v0 + v1 * v1;
                            *reinterpret_cast<float2*>(Cf + (long long)m * D + n) = make_float2(v0, v1);
                        }
                        if (EPI == 0)
                            *reinterpret_cast<float2*>(Cf + (long long)m * D + n) = make_float2(v0, v1);
                        if (EPI < 2) {
                            uint32_t hh, ll;
                            split2(v0, v1, hh, ll);
                            reinterpret_cast<uint32_t*>(Ph)[m * 160 + (n >> 1)] = hh;
                            reinterpret_cast<uint32_t*>(Pl)[m * 160 + (n >> 1)] = ll;
                        }
                    }
                }
            }
        }
    }

    if (EPI == 2) {
        __shared__ float red[256];
        red[tid] = sumsq;
        __syncthreads();
        for (int s = 128; s > 0; s >>= 1) {
            if (tid < s) red[tid] += red[tid + s];
            __syncthreads();
        }
        if (tid == 0) g_partials[blockIdx.x] = red[0];
    }
}

// ---------------- deterministic global reduction -> inv norm ----------------
__global__ void reduce_norm_kernel(int nP) {
    __shared__ float sm[1024];
    float s = 0.f;
    for (int i = threadIdx.x; i < nP; i += 1024) s += g_partials[i];
    sm[threadIdx.x] = s;
    __syncthreads();
    for (int st = 512; st > 0; st >>= 1) {
        if (threadIdx.x < st) sm[threadIdx.x] += sm[threadIdx.x + st];
        __syncthreads();
    }
    if (threadIdx.x == 0) g_inv_norm = 1.0f / sqrtf(sm[0]);
}

// ---------------- in-place scale of output ----------------
__global__ void scale_kernel(float* __restrict__ out) {
    int i = blockIdx.x * blockDim.x + threadIdx.x;
    const int n4 = N_NODES * D / 4;
    if (i < n4) {
        float s = g_inv_norm;
        float4 v = reinterpret_cast<float4*>(out)[i];
        v.x *= s; v.y *= s; v.z *= s; v.w *= s;
        reinterpret_cast<float4*>(out)[i] = v;
    }
}

// ---------------- launch ----------------
extern "C" void kernel_launch(void* const* d_in, const int* in_sizes, int n_in,
                              void* d_out, int out_size)
{
    const float* feat = (const float*)d_in[0];
    const int*   src  = (const int*)  d_in[1];
    const int*   dst  = (const int*)  d_in[2];
    const float* W1   = (const float*)d_in[3];
    const float* b1   = (const float*)d_in[4];
    const float* W2   = (const float*)d_in[5];
    const float* b2   = (const float*)d_in[6];
    const float* W3   = (const float*)d_in[7];
    const float* b3   = (const float*)d_in[8];
    float* out = (float*)d_out;

    float* p_x1;
    uint16_t *p_fh, *p_fl, *p_ah, *p_al, *p_x1h, *p_x1l, *p_x2h, *p_x2l;
    uint4 *p_Wf1, *p_Wf2, *p_Wf3;
    cudaGetSymbolAddress((void**)&p_x1,  g_x1);
    cudaGetSymbolAddress((void**)&p_fh,  g_fh);
    cudaGetSymbolAddress((void**)&p_fl,  g_fl);
    cudaGetSymbolAddress((void**)&p_ah,  g_ah);
    cudaGetSymbolAddress((void**)&p_al,  g_al);
    cudaGetSymbolAddress((void**)&p_x1h, g_x1h);
    cudaGetSymbolAddress((void**)&p_x1l, g_x1l);
    cudaGetSymbolAddress((void**)&p_x2h, g_x2h);
    cudaGetSymbolAddress((void**)&p_x2l, g_x2l);
    cudaGetSymbolAddress((void**)&p_Wf1, g_Wf1);
    cudaGetSymbolAddress((void**)&p_Wf2, g_Wf2);
    cudaGetSymbolAddress((void**)&p_Wf3, g_Wf3);

    const int SMEM_TOTAL = 49152 + 3 * 40960;      // 172032 B
    cudaFuncSetAttribute(gemm_mma<2, 0>, cudaFuncAttributeMaxDynamicSharedMemorySize, SMEM_TOTAL);
    cudaFuncSetAttribute(gemm_mma<2, 1>, cudaFuncAttributeMaxDynamicSharedMemorySize, SMEM_TOTAL);
    cudaFuncSetAttribute(gemm_mma<1, 2>, cudaFuncAttributeMaxDynamicSharedMemorySize, SMEM_TOTAL);

    int eb = (N_EDGES + 255) / 256;                // 3125
    int nb = (N_NODES + 255) / 256;                // 196
    int gb = (N_NODES + 3) / 4;                    // 12500
    int cb = (N_NODES * 75 + 255) / 256;           // 14649
    int gblocks = (N_NODES + 127) / 128;           // 391

    hist_kernel<<<eb, 256>>>(dst);
    partial_kernel<<<nb, 256>>>();
    scanb_kernel<<<1, 256>>>(nb);
    convert_feat_kernel<<<cb, 256>>>(feat);        // <- profiled (4th launch)
    local_scan_kernel<<<nb, 256>>>();
    fill_kernel<<<eb, 256>>>(src, dst);
    prep_w_kernel<<<500, 256>>>(W1, W2, W3);

    gather_kernel<<<gb, 320>>>(feat);
    gemm_mma<2, 0><<<gblocks, 256, SMEM_TOTAL>>>(p_fh, p_fl, p_ah, p_al, p_Wf1, b1,
                                                 p_x1, p_x1h, p_x1l);
    gather_kernel<<<gb, 320>>>(p_x1);
    gemm_mma<2, 1><<<gblocks, 256, SMEM_TOTAL>>>(p_x1h, p_x1l, p_ah, p_al, p_Wf2, b2,
                                                 nullptr, p_x2h, p_x2l);
    gemm_mma<1, 2><<<gblocks, 256, SMEM_TOTAL>>>(p_x2h, p_x2l, p_x2h, p_x2l, p_Wf3, b3,
                                                 out, nullptr, nullptr);

    reduce_norm_kernel<<<1, 1024>>>(gblocks);
    scale_kernel<<<(N_NODES * D / 4 + 255) / 256, 256>>>(out);
}

// round 13
// speedup vs baseline: 1.0251x; 1.0251x over previous
#include <cuda_runtime.h>
#include <math.h>
#include <stdint.h>

#define N_NODES 50000
#define D 300
#define N_EDGES 800000
#define KP 320                      // padded K per plane (bf16 elems), row = 640 B
#define MROWS (N_NODES + 128)       // row padding so cp.async never reads OOB

// ---------------- device scratch (no allocations allowed) ----------------
__device__ __align__(16) float g_x1[N_NODES * D];            // f32 x1 (gather-2 input)
// bf16 hi/lo planes, [MROWS][KP] row-major; pads stay zero (zero-init, never written)
__device__ __align__(16) uint16_t g_fh [MROWS * KP];
__device__ __align__(16) uint16_t g_fl [MROWS * KP];
__device__ __align__(16) uint16_t g_ah [MROWS * KP];
__device__ __align__(16) uint16_t g_al [MROWS * KP];
__device__ __align__(16) uint16_t g_x1h[MROWS * KP];
__device__ __align__(16) uint16_t g_x1l[MROWS * KP];
__device__ __align__(16) uint16_t g_x2h[MROWS * KP];
__device__ __align__(16) uint16_t g_x2l[MROWS * KP];
// fragment-ordered split weights: [kstep][n8t(40)][lane(32)] -> {hi.b0, hi.b1, lo.b0, lo.b1}
__device__ uint4 g_Wf1[40 * 40 * 32];
__device__ uint4 g_Wf2[40 * 40 * 32];
__device__ uint4 g_Wf3[20 * 40 * 32];
// CSR
__device__ int g_count [N_NODES];
__device__ int g_indptr[N_NODES + 1];
__device__ int g_esrc  [N_EDGES];
__device__ int g_bsum[256];
__device__ int g_boff[256];
__device__ float g_partials[4096];
__device__ float g_inv_norm;

// ---------------- helpers ----------------
__device__ __forceinline__ uint32_t smem_u32(const void* p) {
    uint32_t a;
    asm("{ .reg .u64 t; cvta.to.shared.u64 t, %1; cvt.u32.u64 %0, t; }" : "=r"(a) : "l"(p));
    return a;
}
__device__ __forceinline__ uint32_t pack_bf16x2(float e, float o) {
    uint32_t r;
    asm("cvt.rn.bf16x2.f32 %0, %1, %2;" : "=r"(r) : "f"(o), "f"(e));
    return r;
}
__device__ __forceinline__ void split2(float e, float o, uint32_t& hi, uint32_t& lo) {
    hi = pack_bf16x2(e, o);
    float he = __uint_as_float(hi << 16);
    float ho = __uint_as_float(hi & 0xFFFF0000u);
    lo = pack_bf16x2(e - he, o - ho);
}

// ---------------- CSR build ----------------
__global__ void hist_kernel(const int* __restrict__ dst) {
    int e = blockIdx.x * 256 + threadIdx.x;
    if (e < N_EDGES) atomicAdd(&g_count[__ldg(&dst[e])], 1);
}
__global__ void partial_kernel() {
    __shared__ int sh[256];
    int i = blockIdx.x * 256 + threadIdx.x;
    sh[threadIdx.x] = (i < N_NODES) ? g_count[i] : 0;
    __syncthreads();
    for (int s = 128; s > 0; s >>= 1) {
        if (threadIdx.x < s) sh[threadIdx.x] += sh[threadIdx.x + s];
        __syncthreads();
    }
    if (threadIdx.x == 0) g_bsum[blockIdx.x] = sh[0];
}
__global__ void scanb_kernel(int nb) {
    __shared__ int sh[256];
    int v = (threadIdx.x < nb) ? g_bsum[threadIdx.x] : 0;
    sh[threadIdx.x] = v;
    __syncthreads();
    for (int off = 1; off < 256; off <<= 1) {
        int t = (threadIdx.x >= off) ? sh[threadIdx.x - off] : 0;
        __syncthreads();
        sh[threadIdx.x] += t;
        __syncthreads();
    }
    g_boff[threadIdx.x] = sh[threadIdx.x] - v;
}
__global__ void local_scan_kernel() {
    __shared__ int sh[256];
    int i = blockIdx.x * 256 + threadIdx.x;
    int v = (i < N_NODES) ? g_count[i] : 0;
    sh[threadIdx.x] = v;
    __syncthreads();
    for (int off = 1; off < 256; off <<= 1) {
        int t = (threadIdx.x >= off) ? sh[threadIdx.x - off] : 0;
        __syncthreads();
        sh[threadIdx.x] += t;
        __syncthreads();
    }
    if (i < N_NODES) g_indptr[i + 1] = g_boff[blockIdx.x] + sh[threadIdx.x];
    if (i == 0) g_indptr[0] = 0;
}
__global__ void fill_kernel(const int* __restrict__ src, const int* __restrict__ dst) {
    int e = blockIdx.x * 256 + threadIdx.x;
    if (e < N_EDGES) {
        int d = __ldg(&dst[e]);
        int old = atomicAdd(&g_count[d], -1);      // restores g_count to 0
        g_esrc[g_indptr[d] + old - 1] = __ldg(&src[e]);
    }
}

// ---------------- convert feat f32 -> hi/lo planes ----------------
__global__ void convert_feat_kernel(const float* __restrict__ feat) {
    int idx = blockIdx.x * 256 + threadIdx.x;
    if (idx >= N_NODES * 75) return;
    int m = idx / 75, c = idx - m * 75;
    float4 f = reinterpret_cast<const float4*>(feat)[idx];
    uint32_t h0, l0, h1, l1;
    split2(f.x, f.y, h0, l0);
    split2(f.z, f.w, h1, l1);
    reinterpret_cast<uint2*>(g_fh)[m * 80 + c] = make_uint2(h0, h1);
    reinterpret_cast<uint2*>(g_fl)[m * 80 + c] = make_uint2(l0, l1);
}

// ---------------- gather: agg planes = split( sum feat[esrc[j]] ) ----------------
__global__ __launch_bounds__(320)
void gather_kernel(const float* __restrict__ feat) {
    int nl = threadIdx.x / 75;
    int c  = threadIdx.x - nl * 75;
    if (nl >= 4) return;
    int v = blockIdx.x * 4 + nl;
    if (v >= N_NODES) return;
    int beg = __ldg(&g_indptr[v]), end = __ldg(&g_indptr[v + 1]);
    const float4* f4 = reinterpret_cast<const float4*>(feat);
    float4 acc = make_float4(0.f, 0.f, 0.f, 0.f);
    int j = beg;
    for (; j + 1 < end; j += 2) {
        int s0 = __ldg(&g_esrc[j]);
        int s1 = __ldg(&g_esrc[j + 1]);
        float4 a = f4[(long long)s0 * 75 + c];
        float4 b = f4[(long long)s1 * 75 + c];
        acc.x += a.x; acc.y += a.y; acc.z += a.z; acc.w += a.w;
        acc.x += b.x; acc.y += b.y; acc.z += b.z; acc.w += b.w;
    }
    if (j < end) {
        int s0 = __ldg(&g_esrc[j]);
        float4 a = f4[(long long)s0 * 75 + c];
        acc.x += a.x; acc.y += a.y; acc.z += a.z; acc.w += a.w;
    }
    uint32_t h0, l0, h1, l1;
    split2(acc.x, acc.y, h0, l0);
    split2(acc.z, acc.w, h1, l1);
    reinterpret_cast<uint2*>(g_ah)[v * 80 + c] = make_uint2(h0, h1);
    reinterpret_cast<uint2*>(g_al)[v * 80 + c] = make_uint2(l0, l1);
}

// ---------------- prep: split W into fragment-ordered hi/lo, plane-padded ----------------
__global__ void prep_w_kernel(const float* __restrict__ W1,
                              const float* __restrict__ W2,
                              const float* __restrict__ W3) {
    int idx = blockIdx.x * 256 + threadIdx.x;      // 500*256 = 128000 exactly
    const float* W; uint4* out; int K; int rel;
    if (idx < 51200)       { W = W1; out = g_Wf1; K = 600; rel = idx; }
    else if (idx < 102400) { W = W2; out = g_Wf2; K = 600; rel = idx - 51200; }
    else                   { W = W3; out = g_Wf3; K = 300; rel = idx - 102400; }
    int lane  = rel & 31;
    int n8t   = (rel >> 5) % 40;
    int kstep = rel / (40 * 32);
    int plane = kstep / 20, kwp = kstep % 20;
    int n  = n8t * 8 + (lane >> 2);
    int kb = kwp * 16 + (lane & 3) * 2;
    int ks[4] = { kb, kb + 1, kb + 8, kb + 9 };
    float v[4];
#pragma unroll
    for (int i = 0; i < 4; i++) {
        int kg = plane * 300 + ks[i];
        v[i] = (n < D && ks[i] < 300 && kg < K) ? W[(long long)n * K + kg] : 0.f;
    }
    uint32_t h0, l0, h1, l1;
    split2(v[0], v[1], h0, l0);
    split2(v[2], v[3], h1, l1);
    out[rel] = make_uint4(h0, h1, l0, l1);
}

// ---------------- bf16 3-pass split GEMM: A via smem/ldmatrix, B via LDG+reg ping-pong ----
// CTA: BM=128, BN=64, chunk=32 K; 8 warps = 4(M) x 2(N); occ 2.
// B fragments come straight from L2 (fragment-ordered g_Wf), prefetched one
// k16-step ahead into registers -> B never touches the smem crossbar.
// EPI: 0 = lrelu -> Cf + planes, 1 = planes only, 2 = tanh -> Cf + sumsq
template<int NPLANES, int EPI>
__global__ __launch_bounds__(256, 2)
void gemm_mma(const uint16_t* __restrict__ A1h, const uint16_t* __restrict__ A1l,
              const uint16_t* __restrict__ A2h, const uint16_t* __restrict__ A2l,
              const uint4* __restrict__ Wf, const float* __restrict__ bias,
              float* __restrict__ Cf, uint16_t* __restrict__ Ph, uint16_t* __restrict__ Pl)
{
    extern __shared__ char smem[];
    const int T = NPLANES * 10;                    // chunks of K=32
    const int KS = T * 2;                          // total k16 steps

    const uint32_t sb = smem_u32(smem);
    const int tid = threadIdx.x, lane = tid & 31, wid = tid >> 5;
    const int warpM = wid >> 1, warpN = wid & 1;
    const int m0 = blockIdx.y * 128, n0 = blockIdx.x * 64;
    const int n8w = (n0 >> 3) + warpN * 4;         // this warp's first global n8t

    float acc[2][4][4];
#pragma unroll
    for (int mt = 0; mt < 2; mt++)
#pragma unroll
        for (int nt = 0; nt < 4; nt++)
#pragma unroll
            for (int r = 0; r < 4; r++) acc[mt][nt][r] = 0.f;

    auto cpChunk = [&](int t) {
        const int buf = t % 3;
        const int plane = (NPLANES == 2 && t >= 10) ? 1 : 0;
        const int tc = t - plane * 10;
        const uint8_t* ph = (const uint8_t*)(plane ? A2h : A1h);
        const uint8_t* pl = (const uint8_t*)(plane ? A2l : A1l);
#pragma unroll
        for (int i = 0; i < 2; i++) {
            int L = i * 256 + tid;                 // 0..511
            int row = L >> 2, q = L & 3;
            size_t goff = (size_t)(m0 + row) * 640 + tc * 64 + q * 16;
            int sw = q ^ ((row >> 1) & 3);
            uint32_t soff = (uint32_t)(row * 64 + sw * 16);
            asm volatile("cp.async.cg.shared.global [%0], [%1], 16;"
                         :: "r"(sb + (buf * 2 + 0) * 8192 + soff), "l"(ph + goff) : "memory");
            asm volatile("cp.async.cg.shared.global [%0], [%1], 16;"
                         :: "r"(sb + (buf * 2 + 1) * 8192 + soff), "l"(pl + goff) : "memory");
        }
        asm volatile("cp.async.commit_group;" ::: "memory");
    };

    auto ldB = [&](int kstep, uint4* breg) {
#pragma unroll
        for (int nt = 0; nt < 4; nt++)
            breg[nt] = __ldg(&Wf[((size_t)(kstep * 40 + n8w + nt)) * 32 + lane]);
    };

#define MMA_BF16(ACC, AF, B0, B1)                                                 \
    asm volatile(                                                                 \
        "mma.sync.aligned.m16n8k16.row.col.f32.bf16.bf16.f32 "                    \
        "{%0, %1, %2, %3}, {%4, %5, %6, %7}, {%8, %9}, {%0, %1, %2, %3};"         \
        : "+f"((ACC)[0]), "+f"((ACC)[1]), "+f"((ACC)[2]), "+f"((ACC)[3])          \
        : "r"((AF)[0]), "r"((AF)[1]), "r"((AF)[2]), "r"((AF)[3]),                 \
          "r"(B0), "r"(B1))

    // B register ping-pong: bE holds even ksteps, bO holds odd ksteps.
    uint4 bE[4], bO[4];
    ldB(0, bE);

    cpChunk(0);
    cpChunk(1);

    for (int t = 0; t < T; t++) {
        const int buf = t % 3;
        asm volatile("cp.async.wait_group 1;" ::: "memory");
        __syncthreads();
        if (t + 2 < T) cpChunk(t + 2);

#pragma unroll
        for (int k16t = 0; k16t < 2; k16t++) {
            const int kstep = t * 2 + k16t;        // parity == k16t
            // prefetch next kstep's B into the other register bank
            if (kstep + 1 < KS) {
                if (k16t == 0) ldB(kstep + 1, bO);
                else           ldB(kstep + 1, bE);
            }
            const uint4* bf = (k16t == 0) ? bE : bO;

            uint32_t ah[2][4], al[2][4];
            const int rowl = lane & 15;
            const int chunk = k16t * 2 + (lane >> 4);
#pragma unroll
            for (int mt = 0; mt < 2; mt++) {
                int row = warpM * 32 + mt * 16 + rowl;
                uint32_t off = (uint32_t)(row * 64 + ((chunk ^ ((row >> 1) & 3)) * 16));
                asm volatile("ldmatrix.sync.aligned.m8n8.x4.shared.b16 {%0, %1, %2, %3}, [%4];"
                             : "=r"(ah[mt][0]), "=r"(ah[mt][1]), "=r"(ah[mt][2]), "=r"(ah[mt][3])
                             : "r"(sb + (buf * 2 + 0) * 8192 + off));
                asm volatile("ldmatrix.sync.aligned.m8n8.x4.shared.b16 {%0, %1, %2, %3}, [%4];"
                             : "=r"(al[mt][0]), "=r"(al[mt][1]), "=r"(al[mt][2]), "=r"(al[mt][3])
                             : "r"(sb + (buf * 2 + 1) * 8192 + off));
            }
            // pass-major issue order (acc reuse distance 8)
#pragma unroll
            for (int mt = 0; mt < 2; mt++)
#pragma unroll
                for (int nt = 0; nt < 4; nt++)
                    MMA_BF16(acc[mt][nt], ah[mt], bf[nt].x, bf[nt].y);
#pragma unroll
            for (int mt = 0; mt < 2; mt++)
#pragma unroll
                for (int nt = 0; nt < 4; nt++)
                    MMA_BF16(acc[mt][nt], ah[mt], bf[nt].z, bf[nt].w);
#pragma unroll
            for (int mt = 0; mt < 2; mt++)
#pragma unroll
                for (int nt = 0; nt < 4; nt++)
                    MMA_BF16(acc[mt][nt], al[mt], bf[nt].x, bf[nt].y);
        }
    }

    // ---- epilogue ----
    float sumsq = 0.f;
#pragma unroll
    for (int mt = 0; mt < 2; mt++) {
#pragma unroll
        for (int h = 0; h < 2; h++) {
            int m = m0 + warpM * 32 + mt * 16 + (lane >> 2) + h * 8;
            if (m < N_NODES) {
#pragma unroll
                for (int nt = 0; nt < 4; nt++) {
                    int n = n0 + warpN * 32 + nt * 8 + (lane & 3) * 2;
                    if (n < D) {
                        float v0 = acc[mt][nt][h * 2 + 0] + __ldg(&bias[n]);
                        float v1 = acc[mt][nt][h * 2 + 1] + __ldg(&bias[n + 1]);
                        if (EPI == 0) {
                            v0 = (v0 >= 0.f) ? v0 : 0.01f * v0;
                            v1 = (v1 >= 0.f) ? v1 : 0.01f * v1;
                        }
                        if (EPI == 2) {
                            v0 = tanhf(v0); v1 = tanhf(v1);
                            sumsq += v0 * v0 + v1 * v1;
                            *reinterpret_cast<float2*>(Cf + (long long)m * D + n) = make_float2(v0, v1);
                        }
                        if (EPI == 0)
                            *reinterpret_cast<float2*>(Cf + (long long)m * D + n) = make_float2(v0, v1);
                        if (EPI < 2) {
                            uint32_t hh, ll;
                            split2(v0, v1, hh, ll);
                            reinterpret_cast<uint32_t*>(Ph)[m * 160 + (n >> 1)] = hh;
                            reinterpret_cast<uint32_t*>(Pl)[m * 160 + (n >> 1)] = ll;
                        }
                    }
                }
            }
        }
    }

    if (EPI == 2) {
        __shared__ float red[256];
        red[tid] = sumsq;
        __syncthreads();
        for (int s = 128; s > 0; s >>= 1) {
            if (tid < s) red[tid] += red[tid + s];
            __syncthreads();
        }
        if (tid == 0) g_partials[blockIdx.y * gridDim.x + blockIdx.x] = red[0];
    }
}

// ---------------- deterministic global reduction -> inv norm ----------------
__global__ void reduce_norm_kernel(int nP) {
    __shared__ float sm[1024];
    float s = 0.f;
    for (int i = threadIdx.x; i < nP; i += 1024) s += g_partials[i];
    sm[threadIdx.x] = s;
    __syncthreads();
    for (int st = 512; st > 0; st >>= 1) {
        if (threadIdx.x < st) sm[threadIdx.x] += sm[threadIdx.x + st];
        __syncthreads();
    }
    if (threadIdx.x == 0) g_inv_norm = 1.0f / sqrtf(sm[0]);
}

// ---------------- in-place scale of output ----------------
__global__ void scale_kernel(float* __restrict__ out) {
    int i = blockIdx.x * blockDim.x + threadIdx.x;
    const int n4 = N_NODES * D / 4;
    if (i < n4) {
        float s = g_inv_norm;
        float4 v = reinterpret_cast<float4*>(out)[i];
        v.x *= s; v.y *= s; v.z *= s; v.w *= s;
        reinterpret_cast<float4*>(out)[i] = v;
    }
}

// ---------------- launch ----------------
extern "C" void kernel_launch(void* const* d_in, const int* in_sizes, int n_in,
                              void* d_out, int out_size)
{
    const float* feat = (const float*)d_in[0];
    const int*   src  = (const int*)  d_in[1];
    const int*   dst  = (const int*)  d_in[2];
    const float* W1   = (const float*)d_in[3];
    const float* b1   = (const float*)d_in[4];
    const float* W2   = (const float*)d_in[5];
    const float* b2   = (const float*)d_in[6];
    const float* W3   = (const float*)d_in[7];
    const float* b3   = (const float*)d_in[8];
    float* out = (float*)d_out;

    float* p_x1;
    uint16_t *p_fh, *p_fl, *p_ah, *p_al, *p_x1h, *p_x1l, *p_x2h, *p_x2l;
    uint4 *p_Wf1, *p_Wf2, *p_Wf3;
    cudaGetSymbolAddress((void**)&p_x1,  g_x1);
    cudaGetSymbolAddress((void**)&p_fh,  g_fh);
    cudaGetSymbolAddress((void**)&p_fl,  g_fl);
    cudaGetSymbolAddress((void**)&p_ah,  g_ah);
    cudaGetSymbolAddress((void**)&p_al,  g_al);
    cudaGetSymbolAddress((void**)&p_x1h, g_x1h);
    cudaGetSymbolAddress((void**)&p_x1l, g_x1l);
    cudaGetSymbolAddress((void**)&p_x2h, g_x2h);
    cudaGetSymbolAddress((void**)&p_x2l, g_x2l);
    cudaGetSymbolAddress((void**)&p_Wf1, g_Wf1);
    cudaGetSymbolAddress((void**)&p_Wf2, g_Wf2);
    cudaGetSymbolAddress((void**)&p_Wf3, g_Wf3);

    const int SMEM_TOTAL = 49152;                  // A only: 3 bufs x hi/lo x 8KB
    cudaFuncSetAttribute(gemm_mma<2, 0>, cudaFuncAttributeMaxDynamicSharedMemorySize, SMEM_TOTAL);
    cudaFuncSetAttribute(gemm_mma<2, 1>, cudaFuncAttributeMaxDynamicSharedMemorySize, SMEM_TOTAL);
    cudaFuncSetAttribute(gemm_mma<1, 2>, cudaFuncAttributeMaxDynamicSharedMemorySize, SMEM_TOTAL);

    int eb = (N_EDGES + 255) / 256;                // 3125
    int nb = (N_NODES + 255) / 256;                // 196
    int gb = (N_NODES + 3) / 4;                    // 12500
    int cb = (N_NODES * 75 + 255) / 256;           // 14649
    dim3 ggrid((D + 63) / 64, (N_NODES + 127) / 128);   // (5, 391)

    hist_kernel<<<eb, 256>>>(dst);
    partial_kernel<<<nb, 256>>>();
    scanb_kernel<<<1, 256>>>(nb);
    convert_feat_kernel<<<cb, 256>>>(feat);        // <- profiled (4th launch)
    local_scan_kernel<<<nb, 256>>>();
    fill_kernel<<<eb, 256>>>(src, dst);
    prep_w_kernel<<<500, 256>>>(W1, W2, W3);

    gather_kernel<<<gb, 320>>>(feat);
    gemm_mma<2, 0><<<ggrid, 256, SMEM_TOTAL>>>(p_fh, p_fl, p_ah, p_al, p_Wf1, b1,
                                               p_x1, p_x1h, p_x1l);
    gather_kernel<<<gb, 320>>>(p_x1);
    gemm_mma<2, 1><<<ggrid, 256, SMEM_TOTAL>>>(p_x1h, p_x1l, p_ah, p_al, p_Wf2, b2,
                                               nullptr, p_x2h, p_x2l);
    gemm_mma<1, 2><<<ggrid, 256, SMEM_TOTAL>>>(p_x2h, p_x2l, p_x2h, p_x2l, p_Wf3, b3,
                                               out, nullptr, nullptr);

    reduce_norm_kernel<<<1, 1024>>>(ggrid.x * ggrid.y);
    scale_kernel<<<(N_NODES * D / 4 + 255) / 256, 256>>>(out);
}

// round 14
// speedup vs baseline: 1.0384x; 1.0130x over previous
#include <cuda_runtime.h>
#include <math.h>
#include <stdint.h>

#define N_NODES 50000
#define D 300
#define N_EDGES 800000
#define KP 320                      // padded K per plane (bf16 elems), row = 640 B
#define MROWS (N_NODES + 128)       // row padding so cp.async never reads OOB

// ---------------- device scratch (no allocations allowed) ----------------
// bf16 hi/lo planes, [MROWS][KP] row-major; pads stay zero (zero-init, never written)
__device__ __align__(16) uint16_t g_fh [MROWS * KP];
__device__ __align__(16) uint16_t g_fl [MROWS * KP];
__device__ __align__(16) uint16_t g_ah [MROWS * KP];
__device__ __align__(16) uint16_t g_al [MROWS * KP];
__device__ __align__(16) uint16_t g_x1h[MROWS * KP];
__device__ __align__(16) uint16_t g_x1l[MROWS * KP];
__device__ __align__(16) uint16_t g_x2h[MROWS * KP];
__device__ __align__(16) uint16_t g_x2l[MROWS * KP];
// fragment-ordered split weights: [kstep][n8t(40)][lane(32)] -> {hi.b0, hi.b1, lo.b0, lo.b1}
__device__ uint4 g_Wf1[40 * 40 * 32];
__device__ uint4 g_Wf2[40 * 40 * 32];
__device__ uint4 g_Wf3[20 * 40 * 32];
// CSR
__device__ int g_count [N_NODES];
__device__ int g_indptr[N_NODES + 1];
__device__ int g_esrc  [N_EDGES];
__device__ int g_bsum[256];
__device__ int g_boff[256];
__device__ float g_partials[4096];
__device__ float g_inv_norm;

// ---------------- helpers ----------------
__device__ __forceinline__ uint32_t smem_u32(const void* p) {
    uint32_t a;
    asm("{ .reg .u64 t; cvta.to.shared.u64 t, %1; cvt.u32.u64 %0, t; }" : "=r"(a) : "l"(p));
    return a;
}
__device__ __forceinline__ uint32_t pack_bf16x2(float e, float o) {
    uint32_t r;
    asm("cvt.rn.bf16x2.f32 %0, %1, %2;" : "=r"(r) : "f"(o), "f"(e));
    return r;
}
__device__ __forceinline__ void split2(float e, float o, uint32_t& hi, uint32_t& lo) {
    hi = pack_bf16x2(e, o);
    float he = __uint_as_float(hi << 16);
    float ho = __uint_as_float(hi & 0xFFFF0000u);
    lo = pack_bf16x2(e - he, o - ho);
}
// accumulate a (hi,lo) bf16x2 pair into two floats: x += hi+lo (per half)
__device__ __forceinline__ void acc_pair(float& a, float& b, uint32_t h, uint32_t l) {
    a += __uint_as_float(h << 16) + __uint_as_float(l << 16);
    b += __uint_as_float(h & 0xFFFF0000u) + __uint_as_float(l & 0xFFFF0000u);
}

// ---------------- CSR build ----------------
__global__ void hist_kernel(const int* __restrict__ dst) {
    int e = blockIdx.x * 256 + threadIdx.x;
    if (e < N_EDGES) atomicAdd(&g_count[__ldg(&dst[e])], 1);
}
__global__ void partial_kernel() {
    __shared__ int sh[256];
    int i = blockIdx.x * 256 + threadIdx.x;
    sh[threadIdx.x] = (i < N_NODES) ? g_count[i] : 0;
    __syncthreads();
    for (int s = 128; s > 0; s >>= 1) {
        if (threadIdx.x < s) sh[threadIdx.x] += sh[threadIdx.x + s];
        __syncthreads();
    }
    if (threadIdx.x == 0) g_bsum[blockIdx.x] = sh[0];
}
__global__ void scanb_kernel(int nb) {
    __shared__ int sh[256];
    int v = (threadIdx.x < nb) ? g_bsum[threadIdx.x] : 0;
    sh[threadIdx.x] = v;
    __syncthreads();
    for (int off = 1; off < 256; off <<= 1) {
        int t = (threadIdx.x >= off) ? sh[threadIdx.x - off] : 0;
        __syncthreads();
        sh[threadIdx.x] += t;
        __syncthreads();
    }
    g_boff[threadIdx.x] = sh[threadIdx.x] - v;
}
__global__ void local_scan_kernel() {
    __shared__ int sh[256];
    int i = blockIdx.x * 256 + threadIdx.x;
    int v = (i < N_NODES) ? g_count[i] : 0;
    sh[threadIdx.x] = v;
    __syncthreads();
    for (int off = 1; off < 256; off <<= 1) {
        int t = (threadIdx.x >= off) ? sh[threadIdx.x - off] : 0;
        __syncthreads();
        sh[threadIdx.x] += t;
        __syncthreads();
    }
    if (i < N_NODES) g_indptr[i + 1] = g_boff[blockIdx.x] + sh[threadIdx.x];
    if (i == 0) g_indptr[0] = 0;
}
__global__ void fill_kernel(const int* __restrict__ src, const int* __restrict__ dst) {
    int e = blockIdx.x * 256 + threadIdx.x;
    if (e < N_EDGES) {
        int d = __ldg(&dst[e]);
        int old = atomicAdd(&g_count[d], -1);      // restores g_count to 0
        g_esrc[g_indptr[d] + old - 1] = __ldg(&src[e]);
    }
}

// ---------------- gather1 (fused): agg planes + feat conversion ----------------
// 320 threads = 4 nodes x 75 col4. Reads feat f32 (gather loop + own row),
// writes agg hi/lo planes AND feat hi/lo planes.
__global__ __launch_bounds__(320)
void gather_conv_kernel(const float* __restrict__ feat) {
    int nl = threadIdx.x / 75;
    int c  = threadIdx.x - nl * 75;
    if (nl >= 4) return;
    int v = blockIdx.x * 4 + nl;
    if (v >= N_NODES) return;
    int beg = __ldg(&g_indptr[v]), end = __ldg(&g_indptr[v + 1]);
    const float4* f4 = reinterpret_cast<const float4*>(feat);
    float4 acc = make_float4(0.f, 0.f, 0.f, 0.f);
    int j = beg;
    for (; j + 3 < end; j += 4) {                 // 4-way MLP
        int s0 = __ldg(&g_esrc[j]);
        int s1 = __ldg(&g_esrc[j + 1]);
        int s2 = __ldg(&g_esrc[j + 2]);
        int s3 = __ldg(&g_esrc[j + 3]);
        float4 a = f4[(long long)s0 * 75 + c];
        float4 b = f4[(long long)s1 * 75 + c];
        float4 d = f4[(long long)s2 * 75 + c];
        float4 e = f4[(long long)s3 * 75 + c];
        acc.x += a.x + b.x + d.x + e.x;
        acc.y += a.y + b.y + d.y + e.y;
        acc.z += a.z + b.z + d.z + e.z;
        acc.w += a.w + b.w + d.w + e.w;
    }
    for (; j < end; j++) {
        int s0 = __ldg(&g_esrc[j]);
        float4 a = f4[(long long)s0 * 75 + c];
        acc.x += a.x; acc.y += a.y; acc.z += a.z; acc.w += a.w;
    }
    uint32_t h0, l0, h1, l1;
    split2(acc.x, acc.y, h0, l0);
    split2(acc.z, acc.w, h1, l1);
    reinterpret_cast<uint2*>(g_ah)[v * 80 + c] = make_uint2(h0, h1);
    reinterpret_cast<uint2*>(g_al)[v * 80 + c] = make_uint2(l0, l1);
    // fused feat conversion (row is L2-warm)
    float4 f = f4[(long long)v * 75 + c];
    split2(f.x, f.y, h0, l0);
    split2(f.z, f.w, h1, l1);
    reinterpret_cast<uint2*>(g_fh)[v * 80 + c] = make_uint2(h0, h1);
    reinterpret_cast<uint2*>(g_fl)[v * 80 + c] = make_uint2(l0, l1);
}

// ---------------- gather2: agg planes from x1 hi/lo planes (f32 = hi+lo) ----------------
__global__ __launch_bounds__(320)
void gather_planes_kernel(const uint16_t* __restrict__ Xh, const uint16_t* __restrict__ Xl) {
    int nl = threadIdx.x / 75;
    int c  = threadIdx.x - nl * 75;
    if (nl >= 4) return;
    int v = blockIdx.x * 4 + nl;
    if (v >= N_NODES) return;
    int beg = __ldg(&g_indptr[v]), end = __ldg(&g_indptr[v + 1]);
    const uint2* ph = reinterpret_cast<const uint2*>(Xh);
    const uint2* pl = reinterpret_cast<const uint2*>(Xl);
    float4 acc = make_float4(0.f, 0.f, 0.f, 0.f);
    int j = beg;
    for (; j + 1 < end; j += 2) {
        int s0 = __ldg(&g_esrc[j]);
        int s1 = __ldg(&g_esrc[j + 1]);
        uint2 ha = ph[(long long)s0 * 80 + c], la = pl[(long long)s0 * 80 + c];
        uint2 hb = ph[(long long)s1 * 80 + c], lb = pl[(long long)s1 * 80 + c];
        acc_pair(acc.x, acc.y, ha.x, la.x);
        acc_pair(acc.z, acc.w, ha.y, la.y);
        acc_pair(acc.x, acc.y, hb.x, lb.x);
        acc_pair(acc.z, acc.w, hb.y, lb.y);
    }
    if (j < end) {
        int s0 = __ldg(&g_esrc[j]);
        uint2 ha = ph[(long long)s0 * 80 + c], la = pl[(long long)s0 * 80 + c];
        acc_pair(acc.x, acc.y, ha.x, la.x);
        acc_pair(acc.z, acc.w, ha.y, la.y);
    }
    uint32_t h0, l0, h1, l1;
    split2(acc.x, acc.y, h0, l0);
    split2(acc.z, acc.w, h1, l1);
    reinterpret_cast<uint2*>(g_ah)[v * 80 + c] = make_uint2(h0, h1);
    reinterpret_cast<uint2*>(g_al)[v * 80 + c] = make_uint2(l0, l1);
}

// ---------------- prep: split W into fragment-ordered hi/lo, plane-padded ----------------
__global__ void prep_w_kernel(const float* __restrict__ W1,
                              const float* __restrict__ W2,
                              const float* __restrict__ W3) {
    int idx = blockIdx.x * 256 + threadIdx.x;      // 500*256 = 128000 exactly
    const float* W; uint4* out; int K; int rel;
    if (idx < 51200)       { W = W1; out = g_Wf1; K = 600; rel = idx; }
    else if (idx < 102400) { W = W2; out = g_Wf2; K = 600; rel = idx - 51200; }
    else                   { W = W3; out = g_Wf3; K = 300; rel = idx - 102400; }
    int lane  = rel & 31;
    int n8t   = (rel >> 5) % 40;
    int kstep = rel / (40 * 32);
    int plane = kstep / 20, kwp = kstep % 20;
    int n  = n8t * 8 + (lane >> 2);
    int kb = kwp * 16 + (lane & 3) * 2;
    int ks[4] = { kb, kb + 1, kb + 8, kb + 9 };
    float v[4];
#pragma unroll
    for (int i = 0; i < 4; i++) {
        int kg = plane * 300 + ks[i];
        v[i] = (n < D && ks[i] < 300 && kg < K) ? W[(long long)n * K + kg] : 0.f;
    }
    uint32_t h0, l0, h1, l1;
    split2(v[0], v[1], h0, l0);
    split2(v[2], v[3], h1, l1);
    out[rel] = make_uint4(h0, h1, l0, l1);
}

// ---------------- bf16 3-pass split GEMM (R11 config: 3-stage cp.async, pass-major) -----
// CTA: BM=128, BN=64, chunk=32 K; 8 warps = 4(M) x 2(N); occ 2.
// EPI: 0 = lrelu -> planes, 1 = planes, 2 = tanh -> Cf + sumsq
template<int NPLANES, int EPI>
__global__ __launch_bounds__(256, 2)
void gemm_mma(const uint16_t* __restrict__ A1h, const uint16_t* __restrict__ A1l,
              const uint16_t* __restrict__ A2h, const uint16_t* __restrict__ A2l,
              const uint4* __restrict__ Wf, const float* __restrict__ bias,
              float* __restrict__ Cf, uint16_t* __restrict__ Ph, uint16_t* __restrict__ Pl)
{
    extern __shared__ char smem[];
    const int T = NPLANES * 10;
    const int B_OFF = 49152;                       // A: 3 bufs x 2 variants x 8KB

    const uint32_t sb = smem_u32(smem);
    const int tid = threadIdx.x, lane = tid & 31, wid = tid >> 5;
    const int warpM = wid >> 1, warpN = wid & 1;
    const int m0 = blockIdx.y * 128, n0 = blockIdx.x * 64;
    const int n8cta = n0 >> 3;

    float acc[2][4][4];
#pragma unroll
    for (int mt = 0; mt < 2; mt++)
#pragma unroll
        for (int nt = 0; nt < 4; nt++)
#pragma unroll
            for (int r = 0; r < 4; r++) acc[mt][nt][r] = 0.f;

    auto cpChunk = [&](int t) {
        const int buf = t % 3;
        const int plane = (NPLANES == 2 && t >= 10) ? 1 : 0;
        const int tc = t - plane * 10;
        const uint8_t* ph = (const uint8_t*)(plane ? A2h : A1h);
        const uint8_t* pl = (const uint8_t*)(plane ? A2l : A1l);
#pragma unroll
        for (int i = 0; i < 2; i++) {
            int L = i * 256 + tid;                 // 0..511
            int row = L >> 2, q = L & 3;
            size_t goff = (size_t)(m0 + row) * 640 + tc * 64 + q * 16;
            int sw = q ^ ((row >> 1) & 3);
            uint32_t soff = (uint32_t)(row * 64 + sw * 16);
            asm volatile("cp.async.cg.shared.global [%0], [%1], 16;"
                         :: "r"(sb + (buf * 2 + 0) * 8192 + soff), "l"(ph + goff) : "memory");
            asm volatile("cp.async.cg.shared.global [%0], [%1], 16;"
                         :: "r"(sb + (buf * 2 + 1) * 8192 + soff), "l"(pl + goff) : "memory");
        }
#pragma unroll
        for (int i = 0; i < 2; i++) {
            int L = i * 256 + tid;
            int k16t = L >> 8, n8 = (L >> 5) & 7, ln = L & 31;
            const uint4* g = &Wf[((size_t)((t * 2 + k16t) * 40 + n8cta + n8)) * 32 + ln];
            asm volatile("cp.async.cg.shared.global [%0], [%1], 16;"
                         :: "r"(sb + B_OFF + buf * 8192 + (uint32_t)L * 16), "l"(g) : "memory");
        }
        asm volatile("cp.async.commit_group;" ::: "memory");
    };

#define MMA_BF16(ACC, AF, B0, B1)                                                 \
    asm volatile(                                                                 \
        "mma.sync.aligned.m16n8k16.row.col.f32.bf16.bf16.f32 "                    \
        "{%0, %1, %2, %3}, {%4, %5, %6, %7}, {%8, %9}, {%0, %1, %2, %3};"         \
        : "+f"((ACC)[0]), "+f"((ACC)[1]), "+f"((ACC)[2]), "+f"((ACC)[3])          \
        : "r"((AF)[0]), "r"((AF)[1]), "r"((AF)[2]), "r"((AF)[3]),                 \
          "r"(B0), "r"(B1))

    cpChunk(0);
    cpChunk(1);

    for (int t = 0; t < T; t++) {
        const int buf = t % 3;
        asm volatile("cp.async.wait_group 1;" ::: "memory");
        __syncthreads();
        if (t + 2 < T) cpChunk(t + 2);

#pragma unroll
        for (int k16t = 0; k16t < 2; k16t++) {
            uint4 bf[4];
#pragma unroll
            for (int nt = 0; nt < 4; nt++) {
                uint32_t off = sb + B_OFF + buf * 8192 +
                               (uint32_t)((k16t * 8 + warpN * 4 + nt) * 32 + lane) * 16;
                asm volatile("ld.shared.v4.b32 {%0, %1, %2, %3}, [%4];"
                             : "=r"(bf[nt].x), "=r"(bf[nt].y), "=r"(bf[nt].z), "=r"(bf[nt].w)
                             : "r"(off));
            }
            uint32_t ah[2][4], al[2][4];
            const int rowl = lane & 15;
            const int chunk = k16t * 2 + (lane >> 4);
#pragma unroll
            for (int mt = 0; mt < 2; mt++) {
                int row = warpM * 32 + mt * 16 + rowl;
                uint32_t off = (uint32_t)(row * 64 + ((chunk ^ ((row >> 1) & 3)) * 16));
                asm volatile("ldmatrix.sync.aligned.m8n8.x4.shared.b16 {%0, %1, %2, %3}, [%4];"
                             : "=r"(ah[mt][0]), "=r"(ah[mt][1]), "=r"(ah[mt][2]), "=r"(ah[mt][3])
                             : "r"(sb + (buf * 2 + 0) * 8192 + off));
                asm volatile("ldmatrix.sync.aligned.m8n8.x4.shared.b16 {%0, %1, %2, %3}, [%4];"
                             : "=r"(al[mt][0]), "=r"(al[mt][1]), "=r"(al[mt][2]), "=r"(al[mt][3])
                             : "r"(sb + (buf * 2 + 1) * 8192 + off));
            }
            // pass-major issue order (acc reuse distance 8)
#pragma unroll
            for (int mt = 0; mt < 2; mt++)
#pragma unroll
                for (int nt = 0; nt < 4; nt++)
                    MMA_BF16(acc[mt][nt], ah[mt], bf[nt].x, bf[nt].y);
#pragma unroll
            for (int mt = 0; mt < 2; mt++)
#pragma unroll
                for (int nt = 0; nt < 4; nt++)
                    MMA_BF16(acc[mt][nt], ah[mt], bf[nt].z, bf[nt].w);
#pragma unroll
            for (int mt = 0; mt < 2; mt++)
#pragma unroll
                for (int nt = 0; nt < 4; nt++)
                    MMA_BF16(acc[mt][nt], al[mt], bf[nt].x, bf[nt].y);
        }
    }

    // ---- epilogue ----
    float sumsq = 0.f;
#pragma unroll
    for (int mt = 0; mt < 2; mt++) {
#pragma unroll
        for (int h = 0; h < 2; h++) {
            int m = m0 + warpM * 32 + mt * 16 + (lane >> 2) + h * 8;
            if (m < N_NODES) {
#pragma unroll
                for (int nt = 0; nt < 4; nt++) {
                    int n = n0 + warpN * 32 + nt * 8 + (lane & 3) * 2;
                    if (n < D) {
                        float v0 = acc[mt][nt][h * 2 + 0] + __ldg(&bias[n]);
                        float v1 = acc[mt][nt][h * 2 + 1] + __ldg(&bias[n + 1]);
                        if (EPI == 0) {
                            v0 = (v0 >= 0.f) ? v0 : 0.01f * v0;
                            v1 = (v1 >= 0.f) ? v1 : 0.01f * v1;
                        }
                        if (EPI == 2) {
                            v0 = tanhf(v0); v1 = tanhf(v1);
                            sumsq += v0 * v0 + v1 * v1;
                            *reinterpret_cast<float2*>(Cf + (long long)m * D + n) = make_float2(v0, v1);
                        }
                        if (EPI < 2) {
                            uint32_t hh, ll;
                            split2(v0, v1, hh, ll);
                            reinterpret_cast<uint32_t*>(Ph)[m * 160 + (n >> 1)] = hh;
                            reinterpret_cast<uint32_t*>(Pl)[m * 160 + (n >> 1)] = ll;
                        }
                    }
                }
            }
        }
    }

    if (EPI == 2) {
        __shared__ float red[256];
        red[tid] = sumsq;
        __syncthreads();
        for (int s = 128; s > 0; s >>= 1) {
            if (tid < s) red[tid] += red[tid + s];
            __syncthreads();
        }
        if (tid == 0) g_partials[blockIdx.y * gridDim.x + blockIdx.x] = red[0];
    }
}

// ---------------- deterministic global reduction -> inv norm ----------------
__global__ void reduce_norm_kernel(int nP) {
    __shared__ float sm[1024];
    float s = 0.f;
    for (int i = threadIdx.x; i < nP; i += 1024) s += g_partials[i];
    sm[threadIdx.x] = s;
    __syncthreads();
    for (int st = 512; st > 0; st >>= 1) {
        if (threadIdx.x < st) sm[threadIdx.x] += sm[threadIdx.x + st];
        __syncthreads();
    }
    if (threadIdx.x == 0) g_inv_norm = 1.0f / sqrtf(sm[0]);
}

// ---------------- in-place scale of output ----------------
__global__ void scale_kernel(float* __restrict__ out) {
    int i = blockIdx.x * blockDim.x + threadIdx.x;
    const int n4 = N_NODES * D / 4;
    if (i < n4) {
        float s = g_inv_norm;
        float4 v = reinterpret_cast<float4*>(out)[i];
        v.x *= s; v.y *= s; v.z *= s; v.w *= s;
        reinterpret_cast<float4*>(out)[i] = v;
    }
}

// ---------------- launch ----------------
extern "C" void kernel_launch(void* const* d_in, const int* in_sizes, int n_in,
                              void* d_out, int out_size)
{
    const float* feat = (const float*)d_in[0];
    const int*   src  = (const int*)  d_in[1];
    const int*   dst  = (const int*)  d_in[2];
    const float* W1   = (const float*)d_in[3];
    const float* b1   = (const float*)d_in[4];
    const float* W2   = (const float*)d_in[5];
    const float* b2   = (const float*)d_in[6];
    const float* W3   = (const float*)d_in[7];
    const float* b3   = (const float*)d_in[8];
    float* out = (float*)d_out;

    uint16_t *p_fh, *p_fl, *p_ah, *p_al, *p_x1h, *p_x1l, *p_x2h, *p_x2l;
    uint4 *p_Wf1, *p_Wf2, *p_Wf3;
    cudaGetSymbolAddress((void**)&p_fh,  g_fh);
    cudaGetSymbolAddress((void**)&p_fl,  g_fl);
    cudaGetSymbolAddress((void**)&p_ah,  g_ah);
    cudaGetSymbolAddress((void**)&p_al,  g_al);
    cudaGetSymbolAddress((void**)&p_x1h, g_x1h);
    cudaGetSymbolAddress((void**)&p_x1l, g_x1l);
    cudaGetSymbolAddress((void**)&p_x2h, g_x2h);
    cudaGetSymbolAddress((void**)&p_x2l, g_x2l);
    cudaGetSymbolAddress((void**)&p_Wf1, g_Wf1);
    cudaGetSymbolAddress((void**)&p_Wf2, g_Wf2);
    cudaGetSymbolAddress((void**)&p_Wf3, g_Wf3);

    const int SMEM_TOTAL = 49152 + 3 * 8192;       // 72KB (R11 config)
    cudaFuncSetAttribute(gemm_mma<2, 0>, cudaFuncAttributeMaxDynamicSharedMemorySize, SMEM_TOTAL);
    cudaFuncSetAttribute(gemm_mma<2, 1>, cudaFuncAttributeMaxDynamicSharedMemorySize, SMEM_TOTAL);
    cudaFuncSetAttribute(gemm_mma<1, 2>, cudaFuncAttributeMaxDynamicSharedMemorySize, SMEM_TOTAL);

    int eb = (N_EDGES + 255) / 256;                // 3125
    int nb = (N_NODES + 255) / 256;                // 196
    int gb = (N_NODES + 3) / 4;                    // 12500
    dim3 ggrid((D + 63) / 64, (N_NODES + 127) / 128);   // (5, 391)

    hist_kernel<<<eb, 256>>>(dst);
    partial_kernel<<<nb, 256>>>();
    scanb_kernel<<<1, 256>>>(nb);
    local_scan_kernel<<<nb, 256>>>();
    fill_kernel<<<eb, 256>>>(src, dst);
    prep_w_kernel<<<500, 256>>>(W1, W2, W3);

    gather_conv_kernel<<<gb, 320>>>(feat);         // agg planes + feat planes (fused)
    gemm_mma<2, 0><<<ggrid, 256, SMEM_TOTAL>>>(p_fh, p_fl, p_ah, p_al, p_Wf1, b1,
                                               nullptr, p_x1h, p_x1l);
    gather_planes_kernel<<<gb, 320>>>(p_x1h, p_x1l);
    gemm_mma<2, 1><<<ggrid, 256, SMEM_TOTAL>>>(p_x1h, p_x1l, p_ah, p_al, p_Wf2, b2,
                                               nullptr, p_x2h, p_x2l);
    gemm_mma<1, 2><<<ggrid, 256, SMEM_TOTAL>>>(p_x2h, p_x2l, p_x2h, p_x2l, p_Wf3, b3,
                                               out, nullptr, nullptr);

    reduce_norm_kernel<<<1, 1024>>>(ggrid.x * ggrid.y);
    scale_kernel<<<(N_NODES * D / 4 + 255) / 256, 256>>>(out);
}

// round 16
// speedup vs baseline: 1.0801x; 1.0402x over previous
#include <cuda_runtime.h>
#include <math.h>
#include <stdint.h>

#define N_NODES 50000
#define D 300
#define N_EDGES 800000
#define KP 320                      // padded K per plane (bf16 elems), row = 640 B
#define MROWS (N_NODES + 128)       // row padding so cp.async never reads OOB

// ---------------- device scratch (no allocations allowed) ----------------
__device__ __align__(16) float g_x1[N_NODES * D];            // f32 x1 (gather-2 input)
// bf16 hi/lo planes, [MROWS][KP] row-major; pads stay zero (zero-init, never written)
__device__ __align__(16) uint16_t g_fh [MROWS * KP];
__device__ __align__(16) uint16_t g_fl [MROWS * KP];
__device__ __align__(16) uint16_t g_ah [MROWS * KP];
__device__ __align__(16) uint16_t g_al [MROWS * KP];
__device__ __align__(16) uint16_t g_x1h[MROWS * KP];
__device__ __align__(16) uint16_t g_x1l[MROWS * KP];
__device__ __align__(16) uint16_t g_x2h[MROWS * KP];
__device__ __align__(16) uint16_t g_x2l[MROWS * KP];
// fragment-ordered split weights: [kstep][n8t(40)][lane(32)] -> {hi.b0, hi.b1, lo.b0, lo.b1}
__device__ uint4 g_Wf1[40 * 40 * 32];
__device__ uint4 g_Wf2[40 * 40 * 32];
__device__ uint4 g_Wf3[20 * 40 * 32];
// CSR
__device__ int g_count [N_NODES];
__device__ int g_indptr[N_NODES + 1];
__device__ int g_esrc  [N_EDGES];
__device__ int g_bsum[256];
__device__ int g_boff[256];
__device__ float g_partials[4096];
__device__ float g_inv_norm;

// ---------------- helpers ----------------
__device__ __forceinline__ uint32_t smem_u32(const void* p) {
    uint32_t a;
    asm("{ .reg .u64 t; cvta.to.shared.u64 t, %1; cvt.u32.u64 %0, t; }" : "=r"(a) : "l"(p));
    return a;
}
__device__ __forceinline__ uint32_t pack_bf16x2(float e, float o) {
    uint32_t r;
    asm("cvt.rn.bf16x2.f32 %0, %1, %2;" : "=r"(r) : "f"(o), "f"(e));
    return r;
}
__device__ __forceinline__ void split2(float e, float o, uint32_t& hi, uint32_t& lo) {
    hi = pack_bf16x2(e, o);
    float he = __uint_as_float(hi << 16);
    float ho = __uint_as_float(hi & 0xFFFF0000u);
    lo = pack_bf16x2(e - he, o - ho);
}

// ---------------- CSR build ----------------
__global__ void hist_kernel(const int* __restrict__ dst) {
    int e = blockIdx.x * 256 + threadIdx.x;
    if (e < N_EDGES) atomicAdd(&g_count[__ldg(&dst[e])], 1);
}
__global__ void partial_kernel() {
    __shared__ int sh[256];
    int i = blockIdx.x * 256 + threadIdx.x;
    sh[threadIdx.x] = (i < N_NODES) ? g_count[i] : 0;
    __syncthreads();
    for (int s = 128; s > 0; s >>= 1) {
        if (threadIdx.x < s) sh[threadIdx.x] += sh[threadIdx.x + s];
        __syncthreads();
    }
    if (threadIdx.x == 0) g_bsum[blockIdx.x] = sh[0];
}
__global__ void scanb_kernel(int nb) {
    __shared__ int sh[256];
    int v = (threadIdx.x < nb) ? g_bsum[threadIdx.x] : 0;
    sh[threadIdx.x] = v;
    __syncthreads();
    for (int off = 1; off < 256; off <<= 1) {
        int t = (threadIdx.x >= off) ? sh[threadIdx.x - off] : 0;
        __syncthreads();
        sh[threadIdx.x] += t;
        __syncthreads();
    }
    g_boff[threadIdx.x] = sh[threadIdx.x] - v;
}
__global__ void local_scan_kernel() {
    __shared__ int sh[256];
    int i = blockIdx.x * 256 + threadIdx.x;
    int v = (i < N_NODES) ? g_count[i] : 0;
    sh[threadIdx.x] = v;
    __syncthreads();
    for (int off = 1; off < 256; off <<= 1) {
        int t = (threadIdx.x >= off) ? sh[threadIdx.x - off] : 0;
        __syncthreads();
        sh[threadIdx.x] += t;
        __syncthreads();
    }
    if (i < N_NODES) g_indptr[i + 1] = g_boff[blockIdx.x] + sh[threadIdx.x];
    if (i == 0) g_indptr[0] = 0;
}
__global__ void fill_kernel(const int* __restrict__ src, const int* __restrict__ dst) {
    int e = blockIdx.x * 256 + threadIdx.x;
    if (e < N_EDGES) {
        int d = __ldg(&dst[e]);
        int old = atomicAdd(&g_count[d], -1);      // restores g_count to 0
        g_esrc[g_indptr[d] + old - 1] = __ldg(&src[e]);
    }
}

// ---------------- gather1 (fused): agg planes + feat plane conversion ----------------
// EXACT R11 gather inner loop (2-way); tail adds the fused feat split (row L2-warm).
__global__ __launch_bounds__(320)
void gather_conv_kernel(const float* __restrict__ feat) {
    int nl = threadIdx.x / 75;
    int c  = threadIdx.x - nl * 75;
    if (nl >= 4) return;
    int v = blockIdx.x * 4 + nl;
    if (v >= N_NODES) return;
    int beg = __ldg(&g_indptr[v]), end = __ldg(&g_indptr[v + 1]);
    const float4* f4 = reinterpret_cast<const float4*>(feat);
    float4 acc = make_float4(0.f, 0.f, 0.f, 0.f);
    int j = beg;
    for (; j + 1 < end; j += 2) {
        int s0 = __ldg(&g_esrc[j]);
        int s1 = __ldg(&g_esrc[j + 1]);
        float4 a = f4[(long long)s0 * 75 + c];
        float4 b = f4[(long long)s1 * 75 + c];
        acc.x += a.x; acc.y += a.y; acc.z += a.z; acc.w += a.w;
        acc.x += b.x; acc.y += b.y; acc.z += b.z; acc.w += b.w;
    }
    if (j < end) {
        int s0 = __ldg(&g_esrc[j]);
        float4 a = f4[(long long)s0 * 75 + c];
        acc.x += a.x; acc.y += a.y; acc.z += a.z; acc.w += a.w;
    }
    uint32_t h0, l0, h1, l1;
    split2(acc.x, acc.y, h0, l0);
    split2(acc.z, acc.w, h1, l1);
    reinterpret_cast<uint2*>(g_ah)[v * 80 + c] = make_uint2(h0, h1);
    reinterpret_cast<uint2*>(g_al)[v * 80 + c] = make_uint2(l0, l1);
    // fused feat conversion
    float4 f = f4[(long long)v * 75 + c];
    split2(f.x, f.y, h0, l0);
    split2(f.z, f.w, h1, l1);
    reinterpret_cast<uint2*>(g_fh)[v * 80 + c] = make_uint2(h0, h1);
    reinterpret_cast<uint2*>(g_fl)[v * 80 + c] = make_uint2(l0, l1);
}

// ---------------- gather2: agg planes from f32 x1 (EXACT R11 version) ----------------
__global__ __launch_bounds__(320)
void gather_kernel(const float* __restrict__ feat) {
    int nl = threadIdx.x / 75;
    int c  = threadIdx.x - nl * 75;
    if (nl >= 4) return;
    int v = blockIdx.x * 4 + nl;
    if (v >= N_NODES) return;
    int beg = __ldg(&g_indptr[v]), end = __ldg(&g_indptr[v + 1]);
    const float4* f4 = reinterpret_cast<const float4*>(feat);
    float4 acc = make_float4(0.f, 0.f, 0.f, 0.f);
    int j = beg;
    for (; j + 1 < end; j += 2) {
        int s0 = __ldg(&g_esrc[j]);
        int s1 = __ldg(&g_esrc[j + 1]);
        float4 a = f4[(long long)s0 * 75 + c];
        float4 b = f4[(long long)s1 * 75 + c];
        acc.x += a.x; acc.y += a.y; acc.z += a.z; acc.w += a.w;
        acc.x += b.x; acc.y += b.y; acc.z += b.z; acc.w += b.w;
    }
    if (j < end) {
        int s0 = __ldg(&g_esrc[j]);
        float4 a = f4[(long long)s0 * 75 + c];
        acc.x += a.x; acc.y += a.y; acc.z += a.z; acc.w += a.w;
    }
    uint32_t h0, l0, h1, l1;
    split2(acc.x, acc.y, h0, l0);
    split2(acc.z, acc.w, h1, l1);
    reinterpret_cast<uint2*>(g_ah)[v * 80 + c] = make_uint2(h0, h1);
    reinterpret_cast<uint2*>(g_al)[v * 80 + c] = make_uint2(l0, l1);
}

// ---------------- prep: split W into fragment-ordered hi/lo, plane-padded ----------------
__global__ void prep_w_kernel(const float* __restrict__ W1,
                              const float* __restrict__ W2,
                              const float* __restrict__ W3) {
    int idx = blockIdx.x * 256 + threadIdx.x;      // 500*256 = 128000 exactly
    const float* W; uint4* out; int K; int rel;
    if (idx < 51200)       { W = W1; out = g_Wf1; K = 600; rel = idx; }
    else if (idx < 102400) { W = W2; out = g_Wf2; K = 600; rel = idx - 51200; }
    else                   { W = W3; out = g_Wf3; K = 300; rel = idx - 102400; }
    int lane  = rel & 31;
    int n8t   = (rel >> 5) % 40;
    int kstep = rel / (40 * 32);
    int plane = kstep / 20, kwp = kstep % 20;
    int n  = n8t * 8 + (lane >> 2);
    int kb = kwp * 16 + (lane & 3) * 2;
    int ks[4] = { kb, kb + 1, kb + 8, kb + 9 };
    float v[4];
#pragma unroll
    for (int i = 0; i < 4; i++) {
        int kg = plane * 300 + ks[i];
        v[i] = (n < D && ks[i] < 300 && kg < K) ? W[(long long)n * K + kg] : 0.f;
    }
    uint32_t h0, l0, h1, l1;
    split2(v[0], v[1], h0, l0);
    split2(v[2], v[3], h1, l1);
    out[rel] = make_uint4(h0, h1, l0, l1);
}

// ---------------- bf16 3-pass split GEMM (EXACT R11: 3-stage cp.async, pass-major) ------
// CTA: BM=128, BN=64, chunk=32 K; 8 warps = 4(M) x 2(N); occ 2.
// EPI: 0 = lrelu -> Cf + planes, 1 = planes only, 2 = tanh -> Cf + sumsq
template<int NPLANES, int EPI>
__global__ __launch_bounds__(256, 2)
void gemm_mma(const uint16_t* __restrict__ A1h, const uint16_t* __restrict__ A1l,
              const uint16_t* __restrict__ A2h, const uint16_t* __restrict__ A2l,
              const uint4* __restrict__ Wf, const float* __restrict__ bias,
              float* __restrict__ Cf, uint16_t* __restrict__ Ph, uint16_t* __restrict__ Pl)
{
    extern __shared__ char smem[];
    const int T = NPLANES * 10;
    const int B_OFF = 49152;                       // A: 3 bufs x 2 variants x 8KB

    const uint32_t sb = smem_u32(smem);
    const int tid = threadIdx.x, lane = tid & 31, wid = tid >> 5;
    const int warpM = wid >> 1, warpN = wid & 1;
    const int m0 = blockIdx.y * 128, n0 = blockIdx.x * 64;
    const int n8cta = n0 >> 3;

    float acc[2][4][4];
#pragma unroll
    for (int mt = 0; mt < 2; mt++)
#pragma unroll
        for (int nt = 0; nt < 4; nt++)
#pragma unroll
            for (int r = 0; r < 4; r++) acc[mt][nt][r] = 0.f;

    auto cpChunk = [&](int t) {
        const int buf = t % 3;
        const int plane = (NPLANES == 2 && t >= 10) ? 1 : 0;
        const int tc = t - plane * 10;
        const uint8_t* ph = (const uint8_t*)(plane ? A2h : A1h);
        const uint8_t* pl = (const uint8_t*)(plane ? A2l : A1l);
#pragma unroll
        for (int i = 0; i < 2; i++) {
            int L = i * 256 + tid;                 // 0..511
            int row = L >> 2, q = L & 3;
            size_t goff = (size_t)(m0 + row) * 640 + tc * 64 + q * 16;
            int sw = q ^ ((row >> 1) & 3);
            uint32_t soff = (uint32_t)(row * 64 + sw * 16);
            asm volatile("cp.async.cg.shared.global [%0], [%1], 16;"
                         :: "r"(sb + (buf * 2 + 0) * 8192 + soff), "l"(ph + goff) : "memory");
            asm volatile("cp.async.cg.shared.global [%0], [%1], 16;"
                         :: "r"(sb + (buf * 2 + 1) * 8192 + soff), "l"(pl + goff) : "memory");
        }
#pragma unroll
        for (int i = 0; i < 2; i++) {
            int L = i * 256 + tid;
            int k16t = L >> 8, n8 = (L >> 5) & 7, ln = L & 31;
            const uint4* g = &Wf[((size_t)((t * 2 + k16t) * 40 + n8cta + n8)) * 32 + ln];
            asm volatile("cp.async.cg.shared.global [%0], [%1], 16;"
                         :: "r"(sb + B_OFF + buf * 8192 + (uint32_t)L * 16), "l"(g) : "memory");
        }
        asm volatile("cp.async.commit_group;" ::: "memory");
    };

#define MMA_BF16(ACC, AF, B0, B1)                                                 \
    asm volatile(                                                                 \
        "mma.sync.aligned.m16n8k16.row.col.f32.bf16.bf16.f32 "                    \
        "{%0, %1, %2, %3}, {%4, %5, %6, %7}, {%8, %9}, {%0, %1, %2, %3};"         \
        : "+f"((ACC)[0]), "+f"((ACC)[1]), "+f"((ACC)[2]), "+f"((ACC)[3])          \
        : "r"((AF)[0]), "r"((AF)[1]), "r"((AF)[2]), "r"((AF)[3]),                 \
          "r"(B0), "r"(B1))

    cpChunk(0);
    cpChunk(1);

    for (int t = 0; t < T; t++) {
        const int buf = t % 3;
        asm volatile("cp.async.wait_group 1;" ::: "memory");
        __syncthreads();
        if (t + 2 < T) cpChunk(t + 2);

#pragma unroll
        for (int k16t = 0; k16t < 2; k16t++) {
            uint4 bf[4];
#pragma unroll
            for (int nt = 0; nt < 4; nt++) {
                uint32_t off = sb + B_OFF + buf * 8192 +
                               (uint32_t)((k16t * 8 + warpN * 4 + nt) * 32 + lane) * 16;
                asm volatile("ld.shared.v4.b32 {%0, %1, %2, %3}, [%4];"
                             : "=r"(bf[nt].x), "=r"(bf[nt].y), "=r"(bf[nt].z), "=r"(bf[nt].w)
                             : "r"(off));
            }
            uint32_t ah[2][4], al[2][4];
            const int rowl = lane & 15;
            const int chunk = k16t * 2 + (lane >> 4);
#pragma unroll
            for (int mt = 0; mt < 2; mt++) {
                int row = warpM * 32 + mt * 16 + rowl;
                uint32_t off = (uint32_t)(row * 64 + ((chunk ^ ((row >> 1) & 3)) * 16));
                asm volatile("ldmatrix.sync.aligned.m8n8.x4.shared.b16 {%0, %1, %2, %3}, [%4];"
                             : "=r"(ah[mt][0]), "=r"(ah[mt][1]), "=r"(ah[mt][2]), "=r"(ah[mt][3])
                             : "r"(sb + (buf * 2 + 0) * 8192 + off));
                asm volatile("ldmatrix.sync.aligned.m8n8.x4.shared.b16 {%0, %1, %2, %3}, [%4];"
                             : "=r"(al[mt][0]), "=r"(al[mt][1]), "=r"(al[mt][2]), "=r"(al[mt][3])
                             : "r"(sb + (buf * 2 + 1) * 8192 + off));
            }
            // pass-major issue order (acc reuse distance 8)
#pragma unroll
            for (int mt = 0; mt < 2; mt++)
#pragma unroll
                for (int nt = 0; nt < 4; nt++)
                    MMA_BF16(acc[mt][nt], ah[mt], bf[nt].x, bf[nt].y);
#pragma unroll
            for (int mt = 0; mt < 2; mt++)
#pragma unroll
                for (int nt = 0; nt < 4; nt++)
                    MMA_BF16(acc[mt][nt], ah[mt], bf[nt].z, bf[nt].w);
#pragma unroll
            for (int mt = 0; mt < 2; mt++)
#pragma unroll
                for (int nt = 0; nt < 4; nt++)
                    MMA_BF16(acc[mt][nt], al[mt], bf[nt].x, bf[nt].y);
        }
    }

    // ---- epilogue ----
    float sumsq = 0.f;
#pragma unroll
    for (int mt = 0; mt < 2; mt++) {
#pragma unroll
        for (int h = 0; h < 2; h++) {
            int m = m0 + warpM * 32 + mt * 16 + (lane >> 2) + h * 8;
            if (m < N_NODES) {
#pragma unroll
                for (int nt = 0; nt < 4; nt++) {
                    int n = n0 + warpN * 32 + nt * 8 + (lane & 3) * 2;
                    if (n < D) {
                        float v0 = acc[mt][nt][h * 2 + 0] + __ldg(&bias[n]);
                        float v1 = acc[mt][nt][h * 2 + 1] + __ldg(&bias[n + 1]);
                        if (EPI == 0) {
                            v0 = (v0 >= 0.f) ? v0 : 0.01f * v0;
                            v1 = (v1 >= 0.f) ? v1 : 0.01f * v1;
                        }
                        if (EPI == 2) {
                            v0 = tanhf(v0); v1 = tanhf(v1);
                            sumsq += v0 * v0 + v1 * v1;
                            *reinterpret_cast<float2*>(Cf + (long long)m * D + n) = make_float2(v0, v1);
                        }
                        if (EPI == 0)
                            *reinterpret_cast<float2*>(Cf + (long long)m * D + n) = make_float2(v0, v1);
                        if (EPI < 2) {
                            uint32_t hh, ll;
                            split2(v0, v1, hh, ll);
                            reinterpret_cast<uint32_t*>(Ph)[m * 160 + (n >> 1)] = hh;
                            reinterpret_cast<uint32_t*>(Pl)[m * 160 + (n >> 1)] = ll;
                        }
                    }
                }
            }
        }
    }

    if (EPI == 2) {
        __shared__ float red[256];
        red[tid] = sumsq;
        __syncthreads();
        for (int s = 128; s > 0; s >>= 1) {
            if (tid < s) red[tid] += red[tid + s];
            __syncthreads();
        }
        if (tid == 0) g_partials[blockIdx.y * gridDim.x + blockIdx.x] = red[0];
    }
}

// ---------------- deterministic global reduction -> inv norm ----------------
__global__ void reduce_norm_kernel(int nP) {
    __shared__ float sm[1024];
    float s = 0.f;
    for (int i = threadIdx.x; i < nP; i += 1024) s += g_partials[i];
    sm[threadIdx.x] = s;
    __syncthreads();
    for (int st = 512; st > 0; st >>= 1) {
        if (threadIdx.x < st) sm[threadIdx.x] += sm[threadIdx.x + st];
        __syncthreads();
    }
    if (threadIdx.x == 0) g_inv_norm = 1.0f / sqrtf(sm[0]);
}

// ---------------- in-place scale of output ----------------
__global__ void scale_kernel(float* __restrict__ out) {
    int i = blockIdx.x * blockDim.x + threadIdx.x;
    const int n4 = N_NODES * D / 4;
    if (i < n4) {
        float s = g_inv_norm;
        float4 v = reinterpret_cast<float4*>(out)[i];
        v.x *= s; v.y *= s; v.z *= s; v.w *= s;
        reinterpret_cast<float4*>(out)[i] = v;
    }
}

// ---------------- launch ----------------
extern "C" void kernel_launch(void* const* d_in, const int* in_sizes, int n_in,
                              void* d_out, int out_size)
{
    const float* feat = (const float*)d_in[0];
    const int*   src  = (const int*)  d_in[1];
    const int*   dst  = (const int*)  d_in[2];
    const float* W1   = (const float*)d_in[3];
    const float* b1   = (const float*)d_in[4];
    const float* W2   = (const float*)d_in[5];
    const float* b2   = (const float*)d_in[6];
    const float* W3   = (const float*)d_in[7];
    const float* b3   = (const float*)d_in[8];
    float* out = (float*)d_out;

    float* p_x1;
    uint16_t *p_fh, *p_fl, *p_ah, *p_al, *p_x1h, *p_x1l, *p_x2h, *p_x2l;
    uint4 *p_Wf1, *p_Wf2, *p_Wf3;
    cudaGetSymbolAddress((void**)&p_x1,  g_x1);
    cudaGetSymbolAddress((void**)&p_fh,  g_fh);
    cudaGetSymbolAddress((void**)&p_fl,  g_fl);
    cudaGetSymbolAddress((void**)&p_ah,  g_ah);
    cudaGetSymbolAddress((void**)&p_al,  g_al);
    cudaGetSymbolAddress((void**)&p_x1h, g_x1h);
    cudaGetSymbolAddress((void**)&p_x1l, g_x1l);
    cudaGetSymbolAddress((void**)&p_x2h, g_x2h);
    cudaGetSymbolAddress((void**)&p_x2l, g_x2l);
    cudaGetSymbolAddress((void**)&p_Wf1, g_Wf1);
    cudaGetSymbolAddress((void**)&p_Wf2, g_Wf2);
    cudaGetSymbolAddress((void**)&p_Wf3, g_Wf3);

    const int SMEM_TOTAL = 49152 + 3 * 8192;       // 72KB (R11 config)
    cudaFuncSetAttribute(gemm_mma<2, 0>, cudaFuncAttributeMaxDynamicSharedMemorySize, SMEM_TOTAL);
    cudaFuncSetAttribute(gemm_mma<2, 1>, cudaFuncAttributeMaxDynamicSharedMemorySize, SMEM_TOTAL);
    cudaFuncSetAttribute(gemm_mma<1, 2>, cudaFuncAttributeMaxDynamicSharedMemorySize, SMEM_TOTAL);

    int eb = (N_EDGES + 255) / 256;                // 3125
    int nb = (N_NODES + 255) / 256;                // 196
    int gb = (N_NODES + 3) / 4;                    // 12500
    dim3 ggrid((D + 63) / 64, (N_NODES + 127) / 128);   // (5, 391)

    hist_kernel<<<eb, 256>>>(dst);
    partial_kernel<<<nb, 256>>>();
    scanb_kernel<<<1, 256>>>(nb);
    local_scan_kernel<<<nb, 256>>>();
    fill_kernel<<<eb, 256>>>(src, dst);
    prep_w_kernel<<<500, 256>>>(W1, W2, W3);

    gather_conv_kernel<<<gb, 320>>>(feat);         // agg planes + feat planes (fused, 2-way loop)
    gemm_mma<2, 0><<<ggrid, 256, SMEM_TOTAL>>>(p_fh, p_fl, p_ah, p_al, p_Wf1, b1,
                                               p_x1, p_x1h, p_x1l);
    gather_kernel<<<gb, 320>>>(p_x1);              // f32 x1 gather (exact R11)
    gemm_mma<2, 1><<<ggrid, 256, SMEM_TOTAL>>>(p_x1h, p_x1l, p_ah, p_al, p_Wf2, b2,
                                               nullptr, p_x2h, p_x2l);
    gemm_mma<1, 2><<<ggrid, 256, SMEM_TOTAL>>>(p_x2h, p_x2l, p_x2h, p_x2l, p_Wf3, b3,
                                               out, nullptr, nullptr);

    reduce_norm_kernel<<<1, 1024>>>(ggrid.x * ggrid.y);
    scale_kernel<<<(N_NODES * D / 4 + 255) / 256, 256>>>(out);
}